// round 16
// baseline (speedup 1.0000x reference)
#include <cuda_runtime.h>
#include <cuda_fp16.h>
#include <math.h>

#define EDIM   128
#define LSEQ   512
#define NB     16
#define NFEAT  32
#define NBINS  8193
#define LAMBDA 0.01f
#define NBLOCKS 296     // 2 x 148; co-resident at 2 blocks/SM (regs<=128)

typedef unsigned long long u64;

// Persistent scratch. Index p is the PERMUTED bin order (DIF slot order).
__device__ __align__(256) float2 d_X[NB][8200];
__device__ __align__(256) float  d_H1[NB][EDIM * 8];
__device__ __align__(256) __half d_Th[8200][16];   // [TA 0..7 | TB 0..7]

// Self-resetting grid barrier state (zero-init; last-done restores zeros).
__device__ int g_arrive[2];
__device__ int g_go[2];
__device__ int g_done[2];

__device__ __forceinline__ void gridbar(int i) {
    __syncthreads();
    if (threadIdx.x == 0) {
        __threadfence();
        int a = atomicAdd(&g_arrive[i], 1);
        if (a == NBLOCKS - 1) {
            atomicExch(&g_go[i], 1);
        } else {
            while (atomicAdd(&g_go[i], 0) == 0) __nanosleep(64);
        }
        int d = atomicAdd(&g_done[i], 1);
        if (d == NBLOCKS - 1) {
            atomicExch(&g_arrive[i], 0);
            atomicExch(&g_done[i], 0);
            atomicExch(&g_go[i], 0);
        }
        __threadfence();
    }
    __syncthreads();
}

// ---- packed f32x2 helpers ----
__device__ __forceinline__ u64 fma2(u64 a, u64 b, u64 c) {
    u64 d; asm("fma.rn.f32x2 %0, %1, %2, %3;" : "=l"(d) : "l"(a), "l"(b), "l"(c));
    return d;
}
__device__ __forceinline__ u64 add2(u64 a, u64 b) {
    u64 d; asm("add.rn.f32x2 %0, %1, %2;" : "=l"(d) : "l"(a), "l"(b));
    return d;
}
__device__ __forceinline__ u64 pack2(float v) {
    u64 d; asm("mov.b64 %0, {%1, %1};" : "=l"(d) : "f"(v)); return d;
}
__device__ __forceinline__ u64 packpair(float a, float b) {
    u64 d; asm("mov.b64 %0, {%1, %2};" : "=l"(d) : "f"(a), "f"(b)); return d;
}
__device__ __forceinline__ float2 unpack2(u64 p) {
    float2 r; asm("mov.b64 {%0, %1}, %2;" : "=f"(r.x), "=f"(r.y) : "l"(p));
    return r;
}
__device__ __forceinline__ u64 relu2(u64 v) {
    float2 u = unpack2(v);
    return packpair(fmaxf(u.x, 0.0f), fmaxf(u.y, 0.0f));
}
__device__ __forceinline__ u64 h2_to_pk(unsigned int w) {
    float2 f = __half22float2(*(const __half2*)&w);
    return packpair(f.x, f.y);
}
__device__ __forceinline__ float2 cmul(float2 a, float2 b) {
    return make_float2(a.x * b.x - a.y * b.y, a.x * b.y + a.y * b.x);
}
__device__ __forceinline__ float2 cadd(float2 a, float2 b) {
    return make_float2(a.x + b.x, a.y + b.y);
}
__device__ __forceinline__ float2 csub(float2 a, float2 b) {
    return make_float2(a.x - b.x, a.y - b.y);
}

#define PAD(i) ((i) + ((i) >> 4))

// ---------------------------------------------------------------------------
// Single persistent kernel. 296 blocks x 256 threads, 2 blocks/SM guaranteed.
// Phase 1: prep (384 units) -> bar -> Phase 2: gc 2e x 2b (512 units) -> bar
// -> Phase 3: mlp (16 units).
// ---------------------------------------------------------------------------
__global__ void __launch_bounds__(256, 2)
fgn_fused(const float* __restrict__ x, const float* __restrict__ emb,
          const float* __restrict__ w0, const float* __restrict__ b0,
          const float* __restrict__ w1, const float* __restrict__ b1,
          const float* __restrict__ w2, const float* __restrict__ b2,
          const float* __restrict__ emb10,
          const float* __restrict__ fc1w, const float* __restrict__ fc1b,
          const float* __restrict__ fc2w, const float* __restrict__ fc2b,
          const float* __restrict__ fc3w, const float* __restrict__ fc3b,
          float* __restrict__ out) {
    const int bid = blockIdx.x;
    const int tid = threadIdx.x;

    // ======================= PHASE 1: prep =================================
    {
        __shared__ float2 buf[2][546];
        __shared__ float2 tw[256];
        __shared__ float2 w32[2][32];
        const int sub = tid >> 7;
        const int t   = tid & 127;
        float2* B = buf[sub];

        for (int pi = bid; pi < 384; pi += NBLOCKS) {
            const int fftid = pi * 2 + sub;
            const bool fwd = (fftid < 512);
            const int idx = fwd ? fftid : fftid - 512;
            const int r = idx & 31;

            __syncthreads();
            {
                float s, c;
                sincospif((float)tid * (1.0f / 256.0f), &s, &c);
                tw[tid] = make_float2(c, -s);
            }
            if (t < 32) {
                int ph = (r * t) & 31;
                float s, c;
                sincospif((float)ph * (1.0f / 16.0f), &s, &c);
                w32[sub][t] = make_float2(c, -s);
            }
            __syncthreads();

            if (fwd) {
                const int b = idx >> 5;
                #pragma unroll
                for (int li = 0; li < 4; li++) {
                    const int l = t + 128 * li;
                    const float4* xr4 = (const float4*)(x + (b * LSEQ + l) * NFEAT);
                    float sr = 0.0f, si = 0.0f;
                    #pragma unroll
                    for (int i = 0; i < 8; i++) {
                        float4 v4 = xr4[i];
                        float2 wa = w32[sub][4 * i + 0], wb = w32[sub][4 * i + 1];
                        float2 wc = w32[sub][4 * i + 2], wd = w32[sub][4 * i + 3];
                        sr = fmaf(v4.x, wa.x, sr); si = fmaf(v4.x, wa.y, si);
                        sr = fmaf(v4.y, wb.x, sr); si = fmaf(v4.y, wb.y, si);
                        sr = fmaf(v4.z, wc.x, sr); si = fmaf(v4.z, wc.y, si);
                        sr = fmaf(v4.w, wd.x, sr); si = fmaf(v4.w, wd.y, si);
                    }
                    float ss, cc;
                    sincospif((float)(r * l) * (1.0f / 8192.0f), &ss, &cc);
                    B[PAD(l)] = make_float2(fmaf(sr, cc, si * ss), fmaf(si, cc, -sr * ss));
                }
            } else {
                const int j = idx >> 5;
                #pragma unroll
                for (int li = 0; li < 4; li++) {
                    const int l = t + 128 * li;
                    float ev = emb10[l * 8 + j];
                    float ss, cc;
                    sincospif((float)(r * l) * (1.0f / 8192.0f), &ss, &cc);
                    B[PAD(l)] = make_float2(ev * cc, -ev * ss);
                }
            }
            __syncthreads();

            #pragma unroll
            for (int s = 8; s >= 2; s -= 2) {
                const int h = 1 << s, h2 = h >> 1;
                const int j = t & (h2 - 1);
                const int base = ((t >> (s - 1)) << (s + 1)) + j;
                float2 a  = B[PAD(base)];
                float2 bb = B[PAD(base + h2)];
                float2 c  = B[PAD(base + h)];
                float2 d  = B[PAD(base + h + h2)];
                float2 wA = tw[j << (8 - s)];
                float2 wB = tw[(j + h2) << (8 - s)];
                float2 a1 = cadd(a, c),  c1 = cmul(csub(a, c),  wA);
                float2 b1 = cadd(bb, d), d1 = cmul(csub(bb, d), wB);
                float2 w2t = tw[j << (9 - s)];
                B[PAD(base)]          = cadd(a1, b1);
                B[PAD(base + h2)]     = cmul(csub(a1, b1), w2t);
                B[PAD(base + h)]      = cadd(c1, d1);
                B[PAD(base + h + h2)] = cmul(csub(c1, d1), w2t);
                __syncthreads();
            }
            #pragma unroll
            for (int k = 0; k < 2; k++) {
                int i = t + 128 * k;
                float2 u = B[PAD(2 * i)];
                float2 v = B[PAD(2 * i + 1)];
                B[PAD(2 * i)]     = cadd(u, v);
                B[PAD(2 * i + 1)] = csub(u, v);
            }
            __syncthreads();

            if (fwd) {
                const int b = idx >> 5;
                const float sc = 1.0f / 128.0f;
                #pragma unroll
                for (int k = 0; k < 2; k++) {
                    int m = t + 128 * k;
                    float2 v = B[PAD(2 * m)];
                    d_X[b][r * 256 + m] = make_float2(v.x * sc, v.y * sc);
                }
                if (r == 0 && t == 0) {
                    float2 v = B[PAD(1)];
                    d_X[b][8192] = make_float2(v.x * sc, v.y * sc);
                }
            } else {
                const int j = idx >> 5;
                #pragma unroll
                for (int k = 0; k < 2; k++) {
                    int m = t + 128 * k;
                    int p = r * 256 + m;
                    float sf = (p == 0) ? (1.0f / 128.0f) : (2.0f / 128.0f);
                    float2 v = B[PAD(2 * m)];
                    d_Th[p][j]     = __float2half_rn(sf * v.x);
                    d_Th[p][8 + j] = __float2half_rn(sf * v.y);
                }
                if (r == 0 && t == 0) {
                    float2 v = B[PAD(1)];
                    d_Th[8192][j]     = __float2half_rn((1.0f / 128.0f) * v.x);
                    d_Th[8192][8 + j] = __float2half_rn((1.0f / 128.0f) * v.y);
                }
            }
        }
    }

    gridbar(0);

    // ======================= PHASE 2: gc (2e x 2b units) ===================
    {
        __shared__ float red[8][32];
        const int lane = tid & 31, w = tid >> 5;

        for (int ui = bid; ui < 512; ui += NBLOCKS) {
            const int e0  = (ui & 63) * 2;
            const int b0i = (ui >> 6) * 2;

            u64 pD00, pD01, pD01n, pC00, pC01;
            u64 pd10, pd11, pd11n, pC10, pC11;
            u64 pd20, pd21, pd21n, pC20, pC21;
            {
                int eA = e0, eB = e0 + 1;
                float emA = emb[eA], emB = emb[eB];
                float a01 = emA * w0[16384 + eA * 129], q01 = emB * w0[16384 + eB * 129];
                pD00  = packpair(emA * w0[eA * 129], emB * w0[eB * 129]);
                pD01  = packpair(a01, q01);
                pD01n = packpair(-a01, -q01);
                pC00  = packpair(b0[eA], b0[eB]);
                pC01  = packpair(b0[128 + eA], b0[128 + eB]);
                float a11 = w1[16384 + eA * 129], q11 = w1[16384 + eB * 129];
                pd10  = packpair(w1[eA * 129], w1[eB * 129]);
                pd11  = packpair(a11, q11);
                pd11n = packpair(-a11, -q11);
                pC10  = packpair(b1[eA], b1[eB]);
                pC11  = packpair(b1[128 + eA], b1[128 + eB]);
                float a21 = w2[16384 + eA * 129], q21 = w2[16384 + eB * 129];
                pd20  = packpair(w2[eA * 129], w2[eB * 129]);
                pd21  = packpair(a21, q21);
                pd21n = packpair(-a21, -q21);
                pC20  = packpair(b2[eA], b2[eB]);
                pC21  = packpair(b2[128 + eA], b2[128 + eB]);
            }
            const u64 NL = pack2(-LAMBDA);

            u64 acc[2][2][4];
            #pragma unroll
            for (int bb = 0; bb < 2; bb++)
                #pragma unroll
                for (int se = 0; se < 2; se++)
                    #pragma unroll
                    for (int jp = 0; jp < 4; jp++) acc[bb][se][jp] = 0ull;

            for (int p = tid; p < NBINS; p += 256) {
                float2 X0 = d_X[b0i][p];
                float2 X1 = d_X[b0i + 1][p];
                uint4 ha = *(const uint4*)&d_Th[p][0];
                uint4 hb = *(const uint4*)&d_Th[p][8];
                u64 taPk[4], tbPk[4];
                taPk[0] = h2_to_pk(ha.x); taPk[1] = h2_to_pk(ha.y);
                taPk[2] = h2_to_pk(ha.z); taPk[3] = h2_to_pk(ha.w);
                tbPk[0] = h2_to_pk(hb.x); tbPk[1] = h2_to_pk(hb.y);
                tbPk[2] = h2_to_pk(hb.z); tbPk[3] = h2_to_pk(hb.w);
                #pragma unroll
                for (int bb = 0; bb < 2; bb++) {
                    u64 xr2 = pack2(bb ? X1.x : X0.x);
                    u64 xi2 = pack2(bb ? X1.y : X0.y);
                    u64 r1r = fma2(xr2, pD00, fma2(xi2, pD01n, pC00));
                    u64 o1r = relu2(r1r);
                    u64 r1i = fma2(xi2, pD00, fma2(xr2, pD01, pC01));
                    u64 o1i = relu2(r1i);
                    u64 pr = relu2(add2(r1r, NL));
                    u64 pi = relu2(add2(r1i, NL));
                    u64 r2r = fma2(o1r, pd10, fma2(o1i, pd11n, pC10));
                    u64 o2r = relu2(r2r);
                    u64 r2i = fma2(o1i, pd10, fma2(o2r, pd11, pC11));
                    u64 o2i = relu2(r2i);
                    pr = add2(pr, relu2(add2(r2r, NL)));
                    pi = add2(pi, relu2(add2(r2i, NL)));
                    u64 r3r = fma2(o2r, pd20, fma2(o2i, pd21n, pC20));
                    u64 o3r = relu2(r3r);
                    u64 r3i = fma2(o2i, pd20, fma2(o3r, pd21, pC21));
                    u64 zr2 = add2(pr, relu2(add2(r3r, NL)));
                    u64 zi2 = add2(pi, relu2(add2(r3i, NL)));
                    float2 zrv = unpack2(zr2), ziv = unpack2(zi2);
                    {
                        u64 zr = pack2(zrv.x), zi = pack2(ziv.x);
                        u64* A = acc[bb][0];
                        A[0] = fma2(zr, taPk[0], fma2(zi, tbPk[0], A[0]));
                        A[1] = fma2(zr, taPk[1], fma2(zi, tbPk[1], A[1]));
                        A[2] = fma2(zr, taPk[2], fma2(zi, tbPk[2], A[2]));
                        A[3] = fma2(zr, taPk[3], fma2(zi, tbPk[3], A[3]));
                    }
                    {
                        u64 zr = pack2(zrv.y), zi = pack2(ziv.y);
                        u64* A = acc[bb][1];
                        A[0] = fma2(zr, taPk[0], fma2(zi, tbPk[0], A[0]));
                        A[1] = fma2(zr, taPk[1], fma2(zi, tbPk[1], A[1]));
                        A[2] = fma2(zr, taPk[2], fma2(zi, tbPk[2], A[2]));
                        A[3] = fma2(zr, taPk[3], fma2(zi, tbPk[3], A[3]));
                    }
                }
            }

            #pragma unroll
            for (int bb = 0; bb < 2; bb++) {
                #pragma unroll
                for (int se = 0; se < 2; se++) {
                    #pragma unroll
                    for (int jp = 0; jp < 4; jp++) {
                        float2 pv = unpack2(acc[bb][se][jp]);
                        #pragma unroll
                        for (int o = 16; o; o >>= 1) {
                            pv.x += __shfl_down_sync(0xFFFFFFFFu, pv.x, o);
                            pv.y += __shfl_down_sync(0xFFFFFFFFu, pv.y, o);
                        }
                        if (lane == 0) {
                            red[w][bb * 16 + se * 8 + 2 * jp]     = pv.x;
                            red[w][bb * 16 + se * 8 + 2 * jp + 1] = pv.y;
                        }
                    }
                }
                __syncwarp();
            }
            __syncthreads();
            if (tid < 32) {
                float s = 0.0f;
                #pragma unroll
                for (int ww = 0; ww < 8; ww++) s += red[ww][tid];
                d_H1[b0i + (tid >> 4)][e0 * 8 + (tid & 15)] = s;
            }
            __syncthreads();   // protect red[] reuse across units
        }
    }

    gridbar(1);

    // ======================= PHASE 3: mlp ==================================
    if (bid < NB) {
        __shared__ __align__(16) float h[1024];
        __shared__ __align__(16) float v1[64];
        __shared__ __align__(16) float v2[256];
        __shared__ float xs[LSEQ];
        __shared__ float Ps[8];
        const int b = bid;
        const int w = tid >> 5, lane = tid & 31;

        xs[tid]       = x[(b * LSEQ + tid) * NFEAT];
        xs[tid + 256] = x[(b * LSEQ + tid + 256) * NFEAT];
        __syncthreads();
        {
            float s = 0.0f;
            #pragma unroll
            for (int i = 0; i < 16; i++)
                s += xs[lane + 32 * i] * emb10[(lane + 32 * i) * 8 + w];
            #pragma unroll
            for (int o = 16; o; o >>= 1) s += __shfl_down_sync(0xFFFFFFFFu, s, o);
            if (lane == 0) Ps[w] = s;
        }
        __syncthreads();

        #pragma unroll
        for (int k = 0; k < 4; k++) {
            int i = tid + 256 * k;
            h[i] = d_H1[b][i] + emb[i >> 3] * Ps[i & 7];
        }
        __syncthreads();

        // fc1: 64 outputs, 4 threads each
        {
            const int j = tid >> 2, sub = tid & 3;
            const float4* fw = (const float4*)(fc1w + j * 1024);
            const float4* h4 = (const float4*)h;
            float s = 0.0f;
            #pragma unroll
            for (int i = 0; i < 64; i++) {
                float4 a = fw[sub + 4 * i];
                float4 v = h4[sub + 4 * i];
                s += a.x * v.x + a.y * v.y + a.z * v.z + a.w * v.w;
            }
            s += __shfl_down_sync(0xFFFFFFFFu, s, 2, 4);
            s += __shfl_down_sync(0xFFFFFFFFu, s, 1, 4);
            if (sub == 0) {
                s += fc1b[j];
                v1[j] = s > 0.0f ? s : 0.01f * s;
            }
        }
        __syncthreads();

        // fc2: 256 outputs, 1 thread each
        {
            const int j = tid;
            const float4* fw = (const float4*)(fc2w + j * 64);
            const float4* v14 = (const float4*)v1;
            float s = fc2b[j];
            #pragma unroll
            for (int i = 0; i < 16; i++) {
                float4 a = fw[i]; float4 v = v14[i];
                s += a.x * v.x + a.y * v.y + a.z * v.z + a.w * v.w;
            }
            v2[j] = s > 0.0f ? s : 0.01f * s;
        }
        __syncthreads();

        // fc3: 96 outputs, 2 threads each
        if (tid < 192) {
            const int j = tid >> 1, sub = tid & 1;
            const float4* fw = (const float4*)(fc3w + j * 256);
            const float4* v24 = (const float4*)v2;
            float s = 0.0f;
            #pragma unroll
            for (int i = 0; i < 32; i++) {
                float4 a = fw[sub * 32 + i];
                float4 v = v24[sub * 32 + i];
                s += a.x * v.x + a.y * v.y + a.z * v.z + a.w * v.w;
            }
            s += __shfl_down_sync(0xFFFFFFFFu, s, 1, 2);
            if (sub == 0) out[b * 96 + j] = s + fc3b[j];
        }
    }
}

// ---------------------------------------------------------------------------
extern "C" void kernel_launch(void* const* d_in, const int* in_sizes, int n_in,
                              void* d_out, int out_size) {
    const float* x     = (const float*)d_in[0];
    const float* emb   = (const float*)d_in[1];
    const float* w0    = (const float*)d_in[2];
    const float* b0    = (const float*)d_in[3];
    const float* w1    = (const float*)d_in[4];
    const float* b1    = (const float*)d_in[5];
    const float* w2    = (const float*)d_in[6];
    const float* b2    = (const float*)d_in[7];
    const float* emb10 = (const float*)d_in[8];
    const float* fc1w  = (const float*)d_in[9];
    const float* fc1b  = (const float*)d_in[10];
    const float* fc2w  = (const float*)d_in[11];
    const float* fc2b  = (const float*)d_in[12];
    const float* fc3w  = (const float*)d_in[13];
    const float* fc3b  = (const float*)d_in[14];
    float* out = (float*)d_out;

    fgn_fused<<<NBLOCKS, 256>>>(x, emb, w0, b0, w1, b1, w2, b2, emb10,
                                fc1w, fc1b, fc2w, fc2b, fc3w, fc3b, out);
}

// round 17
// speedup vs baseline: 1.0635x; 1.0635x over previous
#include <cuda_runtime.h>
#include <cuda_fp16.h>
#include <math.h>

#define EDIM   128
#define LSEQ   512
#define NB     16
#define NFEAT  32
#define NBINS  8193
#define LAMBDA 0.01f

typedef unsigned long long u64;

// Persistent scratch. Index p is the PERMUTED bin order (DIF slot order):
// p = r*256 + m holds f = 32*rev9(2m) + r ; p = 8192 holds f = 8192.
__device__ __align__(256) float2 d_X[NB][8200];
__device__ __align__(256) float  d_H1[NB][EDIM * 8];
__device__ __align__(256) __half d_Th[8200][16];   // [TA 0..7 | TB 0..7]

// ---- packed f32x2 helpers ----
__device__ __forceinline__ u64 fma2(u64 a, u64 b, u64 c) {
    u64 d; asm("fma.rn.f32x2 %0, %1, %2, %3;" : "=l"(d) : "l"(a), "l"(b), "l"(c));
    return d;
}
__device__ __forceinline__ u64 add2(u64 a, u64 b) {
    u64 d; asm("add.rn.f32x2 %0, %1, %2;" : "=l"(d) : "l"(a), "l"(b));
    return d;
}
__device__ __forceinline__ u64 pack2(float v) {
    u64 d; asm("mov.b64 %0, {%1, %1};" : "=l"(d) : "f"(v)); return d;
}
__device__ __forceinline__ u64 packpair(float a, float b) {
    u64 d; asm("mov.b64 %0, {%1, %2};" : "=l"(d) : "f"(a), "f"(b)); return d;
}
__device__ __forceinline__ float2 unpack2(u64 p) {
    float2 r; asm("mov.b64 {%0, %1}, %2;" : "=f"(r.x), "=f"(r.y) : "l"(p));
    return r;
}
__device__ __forceinline__ u64 relu2(u64 v) {
    float2 u = unpack2(v);
    return packpair(fmaxf(u.x, 0.0f), fmaxf(u.y, 0.0f));
}
__device__ __forceinline__ u64 h2_to_pk(unsigned int w) {
    float2 f = __half22float2(*(const __half2*)&w);
    return packpair(f.x, f.y);
}
__device__ __forceinline__ float2 cmul(float2 a, float2 b) {
    return make_float2(a.x * b.x - a.y * b.y, a.x * b.y + a.y * b.x);
}
__device__ __forceinline__ float2 cadd(float2 a, float2 b) {
    return make_float2(a.x + b.x, a.y + b.y);
}
__device__ __forceinline__ float2 csub(float2 a, float2 b) {
    return make_float2(a.x - b.x, a.y - b.y);
}

#define PAD(i) ((i) + ((i) >> 4))

// ---------------------------------------------------------------------------
// Kernel 1: PREP (R8 radix-4 DIF; writes fp16 table). 384 blocks x 256 thr.
// ---------------------------------------------------------------------------
__global__ void __launch_bounds__(256)
prep(const float* __restrict__ x, const float* __restrict__ emb10) {
    __shared__ float2 buf[2][546];
    __shared__ float2 tw[256];
    __shared__ float2 w32[2][32];
    const int tid = threadIdx.x;
    const int sub = tid >> 7;
    const int t   = tid & 127;
    const int fftid = blockIdx.x * 2 + sub;
    const bool fwd = (fftid < 512);
    const int idx = fwd ? fftid : fftid - 512;
    const int r = idx & 31;
    float2* B = buf[sub];

    {
        float s, c;
        sincospif((float)tid * (1.0f / 256.0f), &s, &c);
        tw[tid] = make_float2(c, -s);
    }
    if (t < 32) {
        int ph = (r * t) & 31;
        float s, c;
        sincospif((float)ph * (1.0f / 16.0f), &s, &c);
        w32[sub][t] = make_float2(c, -s);
    }
    __syncthreads();

    if (fwd) {
        const int b = idx >> 5;
        #pragma unroll
        for (int li = 0; li < 4; li++) {
            const int l = t + 128 * li;
            const float4* xr4 = (const float4*)(x + (b * LSEQ + l) * NFEAT);
            float sr = 0.0f, si = 0.0f;
            #pragma unroll
            for (int i = 0; i < 8; i++) {
                float4 v4 = xr4[i];
                float2 wa = w32[sub][4 * i + 0], wb = w32[sub][4 * i + 1];
                float2 wc = w32[sub][4 * i + 2], wd = w32[sub][4 * i + 3];
                sr = fmaf(v4.x, wa.x, sr); si = fmaf(v4.x, wa.y, si);
                sr = fmaf(v4.y, wb.x, sr); si = fmaf(v4.y, wb.y, si);
                sr = fmaf(v4.z, wc.x, sr); si = fmaf(v4.z, wc.y, si);
                sr = fmaf(v4.w, wd.x, sr); si = fmaf(v4.w, wd.y, si);
            }
            float ss, cc;
            sincospif((float)(r * l) * (1.0f / 8192.0f), &ss, &cc);
            B[PAD(l)] = make_float2(fmaf(sr, cc, si * ss), fmaf(si, cc, -sr * ss));
        }
    } else {
        const int j = idx >> 5;
        #pragma unroll
        for (int li = 0; li < 4; li++) {
            const int l = t + 128 * li;
            float ev = emb10[l * 8 + j];
            float ss, cc;
            sincospif((float)(r * l) * (1.0f / 8192.0f), &ss, &cc);
            B[PAD(l)] = make_float2(ev * cc, -ev * ss);
        }
    }
    __syncthreads();

    #pragma unroll
    for (int s = 8; s >= 2; s -= 2) {
        const int h = 1 << s, h2 = h >> 1;
        const int j = t & (h2 - 1);
        const int base = ((t >> (s - 1)) << (s + 1)) + j;
        float2 a  = B[PAD(base)];
        float2 bb = B[PAD(base + h2)];
        float2 c  = B[PAD(base + h)];
        float2 d  = B[PAD(base + h + h2)];
        float2 wA = tw[j << (8 - s)];
        float2 wB = tw[(j + h2) << (8 - s)];
        float2 a1 = cadd(a, c),  c1 = cmul(csub(a, c),  wA);
        float2 b1 = cadd(bb, d), d1 = cmul(csub(bb, d), wB);
        float2 w2 = tw[j << (9 - s)];
        B[PAD(base)]          = cadd(a1, b1);
        B[PAD(base + h2)]     = cmul(csub(a1, b1), w2);
        B[PAD(base + h)]      = cadd(c1, d1);
        B[PAD(base + h + h2)] = cmul(csub(c1, d1), w2);
        __syncthreads();
    }
    #pragma unroll
    for (int k = 0; k < 2; k++) {
        int i = t + 128 * k;
        float2 u = B[PAD(2 * i)];
        float2 v = B[PAD(2 * i + 1)];
        B[PAD(2 * i)]     = cadd(u, v);
        B[PAD(2 * i + 1)] = csub(u, v);
    }
    __syncthreads();

    if (fwd) {
        const int b = idx >> 5;
        const float sc = 1.0f / 128.0f;
        #pragma unroll
        for (int k = 0; k < 2; k++) {
            int m = t + 128 * k;
            float2 v = B[PAD(2 * m)];
            d_X[b][r * 256 + m] = make_float2(v.x * sc, v.y * sc);
        }
        if (r == 0 && t == 0) {
            float2 v = B[PAD(1)];
            d_X[b][8192] = make_float2(v.x * sc, v.y * sc);
        }
    } else {
        const int j = idx >> 5;
        #pragma unroll
        for (int k = 0; k < 2; k++) {
            int m = t + 128 * k;
            int p = r * 256 + m;
            float sf = (p == 0) ? (1.0f / 128.0f) : (2.0f / 128.0f);
            float2 v = B[PAD(2 * m)];
            d_Th[p][j]     = __float2half_rn(sf * v.x);
            d_Th[p][8 + j] = __float2half_rn(sf * v.y);
        }
        if (r == 0 && t == 0) {
            float2 v = B[PAD(1)];
            d_Th[8192][j]     = __float2half_rn((1.0f / 128.0f) * v.x);
            d_Th[8192][8 + j] = __float2half_rn((1.0f / 128.0f) * v.y);
        }
    }
}

// chain + accumulate for one bin (uses enclosing-scope constants/acc)
#define GC_BODY(X0v, X1v, hav, hbv)                                          \
    do {                                                                      \
        u64 taPk0 = h2_to_pk((hav).x), taPk1 = h2_to_pk((hav).y);             \
        u64 taPk2 = h2_to_pk((hav).z), taPk3 = h2_to_pk((hav).w);             \
        u64 tbPk0 = h2_to_pk((hbv).x), tbPk1 = h2_to_pk((hbv).y);             \
        u64 tbPk2 = h2_to_pk((hbv).z), tbPk3 = h2_to_pk((hbv).w);             \
        _Pragma("unroll")                                                     \
        for (int bb = 0; bb < 2; bb++) {                                      \
            u64 xr2 = pack2(bb ? (X1v).x : (X0v).x);                          \
            u64 xi2 = pack2(bb ? (X1v).y : (X0v).y);                          \
            u64 r1r = fma2(xr2, pD00, fma2(xi2, pD01n, pC00));                \
            u64 o1r = relu2(r1r);                                             \
            u64 r1i = fma2(xi2, pD00, fma2(xr2, pD01, pC01));                 \
            u64 o1i = relu2(r1i);                                             \
            u64 pr = relu2(add2(r1r, NL));                                    \
            u64 pi = relu2(add2(r1i, NL));                                    \
            u64 r2r = fma2(o1r, pd10, fma2(o1i, pd11n, pC10));                \
            u64 o2r = relu2(r2r);                                             \
            u64 r2i = fma2(o1i, pd10, fma2(o2r, pd11, pC11));                 \
            u64 o2i = relu2(r2i);                                             \
            pr = add2(pr, relu2(add2(r2r, NL)));                              \
            pi = add2(pi, relu2(add2(r2i, NL)));                              \
            u64 r3r = fma2(o2r, pd20, fma2(o2i, pd21n, pC20));                \
            u64 o3r = relu2(r3r);                                             \
            u64 r3i = fma2(o2i, pd20, fma2(o3r, pd21, pC21));                 \
            u64 zr2 = add2(pr, relu2(add2(r3r, NL)));                         \
            u64 zi2 = add2(pi, relu2(add2(r3i, NL)));                         \
            float2 zrv = unpack2(zr2), ziv = unpack2(zi2);                    \
            {                                                                 \
                u64 zr = pack2(zrv.x), zi = pack2(ziv.x);                     \
                u64* A = acc[bb][0];                                          \
                A[0] = fma2(zr, taPk0, fma2(zi, tbPk0, A[0]));                \
                A[1] = fma2(zr, taPk1, fma2(zi, tbPk1, A[1]));                \
                A[2] = fma2(zr, taPk2, fma2(zi, tbPk2, A[2]));                \
                A[3] = fma2(zr, taPk3, fma2(zi, tbPk3, A[3]));                \
            }                                                                 \
            {                                                                 \
                u64 zr = pack2(zrv.y), zi = pack2(ziv.y);                     \
                u64* A = acc[bb][1];                                          \
                A[0] = fma2(zr, taPk0, fma2(zi, tbPk0, A[0]));                \
                A[1] = fma2(zr, taPk1, fma2(zi, tbPk1, A[1]));                \
                A[2] = fma2(zr, taPk2, fma2(zi, tbPk2, A[2]));                \
                A[3] = fma2(zr, taPk3, fma2(zi, tbPk3, A[3]));                \
            }                                                                 \
        }                                                                     \
    } while (0)

// ---------------------------------------------------------------------------
// Kernel 2: gc_gemm, 2e x 2b tile, fp16 table, dual-bin ILP body.
// Grid (64, 8) x 256 threads, 2 blocks/SM.
// ---------------------------------------------------------------------------
__global__ void __launch_bounds__(256, 2)
gc_gemm(const float* __restrict__ emb,
        const float* __restrict__ w0, const float* __restrict__ b0,
        const float* __restrict__ w1, const float* __restrict__ b1,
        const float* __restrict__ w2, const float* __restrict__ b2) {
    const int e0  = blockIdx.x * 2;
    const int b0i = blockIdx.y * 2;
    const int tid = threadIdx.x;

    u64 pD00, pD01, pD01n, pC00, pC01;
    u64 pd10, pd11, pd11n, pC10, pC11;
    u64 pd20, pd21, pd21n, pC20, pC21;
    {
        int eA = e0, eB = e0 + 1;
        float emA = emb[eA], emB = emb[eB];
        float a01 = emA * w0[16384 + eA * 129], q01 = emB * w0[16384 + eB * 129];
        pD00  = packpair(emA * w0[eA * 129], emB * w0[eB * 129]);
        pD01  = packpair(a01, q01);
        pD01n = packpair(-a01, -q01);
        pC00  = packpair(b0[eA], b0[eB]);
        pC01  = packpair(b0[128 + eA], b0[128 + eB]);
        float a11 = w1[16384 + eA * 129], q11 = w1[16384 + eB * 129];
        pd10  = packpair(w1[eA * 129], w1[eB * 129]);
        pd11  = packpair(a11, q11);
        pd11n = packpair(-a11, -q11);
        pC10  = packpair(b1[eA], b1[eB]);
        pC11  = packpair(b1[128 + eA], b1[128 + eB]);
        float a21 = w2[16384 + eA * 129], q21 = w2[16384 + eB * 129];
        pd20  = packpair(w2[eA * 129], w2[eB * 129]);
        pd21  = packpair(a21, q21);
        pd21n = packpair(-a21, -q21);
        pC20  = packpair(b2[eA], b2[eB]);
        pC21  = packpair(b2[128 + eA], b2[128 + eB]);
    }
    const u64 NL = pack2(-LAMBDA);

    u64 acc[2][2][4];   // [bb][sub-e][j-pair]
    #pragma unroll
    for (int bb = 0; bb < 2; bb++)
        #pragma unroll
        for (int se = 0; se < 2; se++)
            #pragma unroll
            for (int jp = 0; jp < 4; jp++) acc[bb][se][jp] = 0ull;

    // uniform 16 iterations, 2 independent bins each (covers p = 0..8191)
    for (int k = 0; k < 16; k++) {
        const int pA = tid + 512 * k;
        const int pB = pA + 256;
        float2 XA0 = d_X[b0i][pA];
        float2 XA1 = d_X[b0i + 1][pA];
        float2 XB0 = d_X[b0i][pB];
        float2 XB1 = d_X[b0i + 1][pB];
        uint4 haA = *(const uint4*)&d_Th[pA][0];
        uint4 hbA = *(const uint4*)&d_Th[pA][8];
        uint4 haB = *(const uint4*)&d_Th[pB][0];
        uint4 hbB = *(const uint4*)&d_Th[pB][8];
        GC_BODY(XA0, XA1, haA, hbA);
        GC_BODY(XB0, XB1, haB, hbB);
    }
    // bin 8192 (one thread per block)
    if (tid == 0) {
        float2 XA0 = d_X[b0i][8192];
        float2 XA1 = d_X[b0i + 1][8192];
        uint4 haA = *(const uint4*)&d_Th[8192][0];
        uint4 hbA = *(const uint4*)&d_Th[8192][8];
        GC_BODY(XA0, XA1, haA, hbA);
    }

    __shared__ float red[8][32];
    const int lane = tid & 31, w = tid >> 5;
    #pragma unroll
    for (int bb = 0; bb < 2; bb++) {
        #pragma unroll
        for (int se = 0; se < 2; se++) {
            #pragma unroll
            for (int jp = 0; jp < 4; jp++) {
                float2 pv = unpack2(acc[bb][se][jp]);
                #pragma unroll
                for (int o = 16; o; o >>= 1) {
                    pv.x += __shfl_down_sync(0xFFFFFFFFu, pv.x, o);
                    pv.y += __shfl_down_sync(0xFFFFFFFFu, pv.y, o);
                }
                if (lane == 0) {
                    red[w][bb * 16 + se * 8 + 2 * jp]     = pv.x;
                    red[w][bb * 16 + se * 8 + 2 * jp + 1] = pv.y;
                }
            }
        }
        __syncwarp();
    }
    __syncthreads();
    if (tid < 32) {
        float s = 0.0f;
        #pragma unroll
        for (int ww = 0; ww < 8; ww++) s += red[ww][tid];
        d_H1[b0i + (tid >> 4)][e0 * 8 + (tid & 15)] = s;
    }
}

// ---------------------------------------------------------------------------
// Kernel 3: bias projection + final MLP (R8, proven). 16 blocks x 512 thr.
// ---------------------------------------------------------------------------
__global__ void __launch_bounds__(512)
mlp_kernel(const float* __restrict__ x, const float* __restrict__ emb,
           const float* __restrict__ emb10,
           const float* __restrict__ fc1w, const float* __restrict__ fc1b,
           const float* __restrict__ fc2w, const float* __restrict__ fc2b,
           const float* __restrict__ fc3w, const float* __restrict__ fc3b,
           float* __restrict__ out) {
    __shared__ __align__(16) float h[1024];
    __shared__ __align__(16) float v1[64];
    __shared__ __align__(16) float v2[256];
    __shared__ float xs[LSEQ];
    __shared__ float Ps[8];
    const int b = blockIdx.x;
    const int tid = threadIdx.x;
    const int w = tid >> 5, lane = tid & 31;

    xs[tid] = x[(b * LSEQ + tid) * NFEAT];
    __syncthreads();
    if (w < 8) {
        float s = 0.0f;
        #pragma unroll
        for (int i = 0; i < 16; i++)
            s += xs[lane + 32 * i] * emb10[(lane + 32 * i) * 8 + w];
        #pragma unroll
        for (int o = 16; o; o >>= 1) s += __shfl_down_sync(0xFFFFFFFFu, s, o);
        if (lane == 0) Ps[w] = s;
    }
    __syncthreads();

    #pragma unroll
    for (int k = 0; k < 2; k++) {
        int i = tid + 512 * k;
        h[i] = d_H1[b][i] + emb[i >> 3] * Ps[i & 7];
    }
    __syncthreads();

    {
        const int j = tid >> 3, sub = tid & 7;
        const float4* fw = (const float4*)(fc1w + j * 1024);
        const float4* h4 = (const float4*)h;
        float s = 0.0f;
        #pragma unroll
        for (int i = 0; i < 32; i++) {
            float4 a = fw[sub + 8 * i];
            float4 v = h4[sub + 8 * i];
            s += a.x * v.x + a.y * v.y + a.z * v.z + a.w * v.w;
        }
        s += __shfl_down_sync(0xFFFFFFFFu, s, 4, 8);
        s += __shfl_down_sync(0xFFFFFFFFu, s, 2, 8);
        s += __shfl_down_sync(0xFFFFFFFFu, s, 1, 8);
        if (sub == 0) {
            s += fc1b[j];
            v1[j] = s > 0.0f ? s : 0.01f * s;
        }
    }
    __syncthreads();

    {
        const int j = tid >> 1, sub = tid & 1;
        const float4* fw = (const float4*)(fc2w + j * 64);
        const float4* v14 = (const float4*)v1;
        float s = 0.0f;
        #pragma unroll
        for (int i = 0; i < 8; i++) {
            float4 a = fw[sub * 8 + i];
            float4 v = v14[sub * 8 + i];
            s += a.x * v.x + a.y * v.y + a.z * v.z + a.w * v.w;
        }
        s += __shfl_down_sync(0xFFFFFFFFu, s, 1, 2);
        if (sub == 0) {
            s += fc2b[j];
            v2[j] = s > 0.0f ? s : 0.01f * s;
        }
    }
    __syncthreads();

    if (tid < 384) {
        const int j = tid >> 2, sub = tid & 3;
        const float4* fw = (const float4*)(fc3w + j * 256);
        const float4* v24 = (const float4*)v2;
        float s = 0.0f;
        #pragma unroll
        for (int i = 0; i < 16; i++) {
            float4 a = fw[sub * 16 + i];
            float4 v = v24[sub * 16 + i];
            s += a.x * v.x + a.y * v.y + a.z * v.z + a.w * v.w;
        }
        s += __shfl_down_sync(0xFFFFFFFFu, s, 2, 4);
        s += __shfl_down_sync(0xFFFFFFFFu, s, 1, 4);
        if (sub == 0) out[b * 96 + j] = s + fc3b[j];
    }
}

// ---------------------------------------------------------------------------
extern "C" void kernel_launch(void* const* d_in, const int* in_sizes, int n_in,
                              void* d_out, int out_size) {
    const float* x     = (const float*)d_in[0];
    const float* emb   = (const float*)d_in[1];
    const float* w0    = (const float*)d_in[2];
    const float* b0    = (const float*)d_in[3];
    const float* w1    = (const float*)d_in[4];
    const float* b1    = (const float*)d_in[5];
    const float* w2    = (const float*)d_in[6];
    const float* b2    = (const float*)d_in[7];
    const float* emb10 = (const float*)d_in[8];
    const float* fc1w  = (const float*)d_in[9];
    const float* fc1b  = (const float*)d_in[10];
    const float* fc2w  = (const float*)d_in[11];
    const float* fc2b  = (const float*)d_in[12];
    const float* fc3w  = (const float*)d_in[13];
    const float* fc3b  = (const float*)d_in[14];
    float* out = (float*)d_out;

    prep<<<384, 256>>>(x, emb10);
    gc_gemm<<<dim3(64, 8), 256>>>(emb, w0, b0, w1, b1, w2, b2);
    mlp_kernel<<<NB, 512>>>(x, emb, emb10, fc1w, fc1b, fc2w, fc2b, fc3w, fc3b, out);
}